// round 9
// baseline (speedup 1.0000x reference)
#include <cuda_runtime.h>
#include <math.h>

// Problem constants (from reference setup_inputs)
#define B 8
#define C 64
#define SPATIAL (48*48*48)        // 110592 floats per (b,c) channel
#define SPATIAL4 (SPATIAL/4)      // 27648 float4 per channel
#define SEGS 4                    // quarter-row segments
#define SEG4 (SPATIAL4/SEGS)      // 6912 float4 per segment
#define NBLK1 (B*C*SEGS)          // 2048 reduction blocks
#define NTAIL 64                  // tail blocks that compute the MLP rows
#define R 8
#define NEG_SLOPE 0.01f

// Scratch (no cudaMalloc allowed)
__device__ float g_partials[NBLK1];
__device__ int   g_idx[B * R];
__device__ int   g_count = 0;     // arrival ticket (self-resetting)
__device__ int   g_done  = 0;     // tail-completion counter (self-resetting)

// ---------------------------------------------------------------------------
// Kernel 1: quarter-row partial sums + tail MLP/top-k.
// All 2048 blocks reduce one quarter-row. The 64 blocks drawing the last
// tickets spin until every partial is published, then tail block k computes
// the MLP for batch k>>3 and the rank-(k&7) channel -> g_idx[k]. 64 blocks
// concurrently: no single-CTA throttle, deterministic, deadlock-free.
// ---------------------------------------------------------------------------
__global__ __launch_bounds__(256) void mean_mlp_kernel(
    const float* __restrict__ x,
    const float* __restrict__ w1, const float* __restrict__ b1,
    const float* __restrict__ w2, const float* __restrict__ b2) {

    const int blk  = blockIdx.x;          // row*4 + seg
    const int t    = threadIdx.x;
    const int lane = t & 31;
    const int wrp  = t >> 5;              // 0..7

    // ---- Phase A: quarter-row partial sum --------------------------------
    {
        const int row = blk >> 2;
        const int seg = blk & 3;
        const float4* __restrict__ p =
            reinterpret_cast<const float4*>(x + (size_t)row * SPATIAL) + seg * SEG4;

        float ax = 0.f, ay = 0.f, az = 0.f, aw = 0.f;
        // 6912 / 256 = 27 iterations
#pragma unroll 9
        for (int i = t; i < SEG4; i += 256) {
            float4 v = p[i];
            ax += v.x; ay += v.y; az += v.z; aw += v.w;
        }
        float acc = (ax + ay) + (az + aw);

        for (int off = 16; off > 0; off >>= 1)
            acc += __shfl_down_sync(0xFFFFFFFFu, acc, off);

        __shared__ float warp_sums[8];
        if (lane == 0) warp_sums[wrp] = acc;
        __syncthreads();

        if (t == 0) {
            float s = warp_sums[0] + warp_sums[1] + warp_sums[2] + warp_sums[3]
                    + warp_sums[4] + warp_sums[5] + warp_sums[6] + warp_sums[7];
            g_partials[blk] = s;
        }
    }

    // ---- Ticket: last NTAIL arrivals become MLP blocks --------------------
    __shared__ int k_s;
    if (t == 0) {
        __threadfence();                       // release this block's partial
        const int old = atomicAdd(&g_count, 1);
        int k = -1;
        if (old >= NBLK1 - NTAIL) {
            k = NBLK1 - 1 - old;               // 0..63
            while (*(volatile int*)&g_count < NBLK1) __nanosleep(64);
        }
        k_s = k;
    }
    __syncthreads();
    const int k = k_s;
    if (k < 0) return;                         // non-tail blocks exit
    __threadfence();                           // acquire all partials

    // ---- Phase B: warp-cooperative MLP for row k --------------------------
    __shared__ float mb[C];
    __shared__ float y1[C];
    __shared__ float y2[C];

    const int b = k >> 3;
    const int r = k & 7;

    if (t < C) {
        float4 ps = reinterpret_cast<const float4*>(g_partials)[b * C + t];
        mb[t] = ((ps.x + ps.y) + (ps.z + ps.w)) * (1.0f / (float)SPATIAL);
    }
    __syncthreads();

    // layer 1: warp w -> channels 8w..8w+7 (coalesced weight LDG + shuffle)
    {
        const float m0 = mb[lane];
        const float m1 = mb[lane + 32];
#pragma unroll
        for (int c = 0; c < 8; c++) {
            const int i = 8 * wrp + c;
            const float* __restrict__ wr = w1 + i * C;
            float a = m0 * wr[lane] + m1 * wr[lane + 32];
#pragma unroll
            for (int off = 16; off > 0; off >>= 1)
                a += __shfl_down_sync(0xFFFFFFFFu, a, off);
            if (lane == 0) {
                a += b1[i];
                y1[i] = (a > 0.0f) ? a : NEG_SLOPE * a;
            }
        }
    }
    __syncthreads();

    // layer 2: same with w2, sigmoid
    {
        const float h0 = y1[lane];
        const float h1 = y1[lane + 32];
#pragma unroll
        for (int c = 0; c < 8; c++) {
            const int i = 8 * wrp + c;
            const float* __restrict__ wr = w2 + i * C;
            float a = h0 * wr[lane] + h1 * wr[lane + 32];
#pragma unroll
            for (int off = 16; off > 0; off >>= 1)
                a += __shfl_down_sync(0xFFFFFFFFu, a, off);
            if (lane == 0) {
                a += b2[i];
                y2[i] = 1.0f / (1.0f + expf(-a));
            }
        }
    }
    __syncthreads();

    // warp 0: r+1 rounds of warp-parallel argmax; strictly-greater wins,
    // ties keep the smaller index (matches jax.lax.top_k).
    if (t < 32) {
        float v0 = y2[t];
        float v1 = y2[t + 32];
        int sel = 0;
        for (int round = 0; round <= r; round++) {
            float bv; int bj;
            if (v0 >= v1) { bv = v0; bj = t; }
            else          { bv = v1; bj = t + 32; }
#pragma unroll
            for (int off = 16; off > 0; off >>= 1) {
                const float ov = __shfl_down_sync(0xFFFFFFFFu, bv, off);
                const int   oj = __shfl_down_sync(0xFFFFFFFFu, bj, off);
                if (ov > bv || (ov == bv && oj < bj)) { bv = ov; bj = oj; }
            }
            bj = __shfl_sync(0xFFFFFFFFu, bj, 0);
            sel = bj;
            if (bj == t)      v0 = -1.0f;   // sigmoid in (0,1)
            if (bj == t + 32) v1 = -1.0f;
        }
        if (t == 0) g_idx[k] = sel;
    }

    // ---- Reset counters for next graph replay (last tail block) ----------
    if (t == 0) {
        const int d = atomicAdd(&g_done, 1);
        if (d == NTAIL - 1) { g_count = 0; g_done = 0; }
    }
}

// ---------------------------------------------------------------------------
// Kernel 2: pure gather: out[b][r][:] = x[b][g_idx[b*R+r]][:]
// grid = (27, 64), 256 threads, 4 float4/thread (measured 10.6us).
// ---------------------------------------------------------------------------
__global__ __launch_bounds__(256) void gather_kernel(const float* __restrict__ x,
                                                     const int* __restrict__ idx,
                                                     float* __restrict__ out) {
    const int row = blockIdx.y;          // 0..63 : b*R + r
    const int b   = row >> 3;
    const int ch  = __ldg(idx + row);

    const float4* __restrict__ src =
        reinterpret_cast<const float4*>(x + ((size_t)b * C + ch) * SPATIAL);
    float4* __restrict__ dst =
        reinterpret_cast<float4*>(out) + (size_t)row * SPATIAL4;

    const int base = blockIdx.x * (256 * 4) + threadIdx.x;
#pragma unroll
    for (int kk = 0; kk < 4; kk++) {
        const int i = base + kk * 256;
        dst[i] = src[i];   // 27648 = 27*256*4 exactly: no bounds check
    }
}

// ---------------------------------------------------------------------------
extern "C" void kernel_launch(void* const* d_in, const int* in_sizes, int n_in,
                              void* d_out, int out_size) {
    const float* x  = (const float*)d_in[0];
    const float* w1 = (const float*)d_in[1];
    const float* b1 = (const float*)d_in[2];
    const float* w2 = (const float*)d_in[3];
    const float* b2 = (const float*)d_in[4];
    float* out = (float*)d_out;

    int* idx;
    cudaGetSymbolAddress((void**)&idx, g_idx);

    mean_mlp_kernel<<<NBLK1, 256>>>(x, w1, b1, w2, b2);
    dim3 grid(SPATIAL4 / (256 * 4), B * R);   // (27, 64)
    gather_kernel<<<grid, 256>>>(x, idx, out);
}

// round 10
// speedup vs baseline: 1.1287x; 1.1287x over previous
#include <cuda_runtime.h>
#include <math.h>

// Problem constants (from reference setup_inputs)
#define B 8
#define C 64
#define SPATIAL (48*48*48)        // 110592 floats per (b,c) channel
#define SPATIAL4 (SPATIAL/4)      // 27648 float4 per channel
#define SEGS 4                    // quarter-row segments
#define SEG4 (SPATIAL4/SEGS)      // 6912 float4 per segment
#define NBLK1 (B*C*SEGS)          // 2048 reduction blocks
#define R 8
#define NEG_SLOPE 0.01f

// gather kernel geometry: 6 chunks per row, 512 threads, 9 float4/thread
#define GT 512
#define GK 9
#define GBX 6                     // 6*512*9 = 27648 = SPATIAL4 exactly

// Scratch (no cudaMalloc allowed)
__device__ float g_partials[NBLK1];

// ---------------------------------------------------------------------------
// Kernel 1: quarter-row partial sums. 2048 blocks x 256 threads.
// Each block fires the PDL trigger right after publishing its partial so the
// gather kernel can begin staging weights while this kernel's tail drains.
// ---------------------------------------------------------------------------
__global__ __launch_bounds__(256) void mean_partial_kernel(
    const float* __restrict__ x, float* __restrict__ partials) {
    const int blk = blockIdx.x;          // row*4 + seg
    const int row = blk >> 2;
    const int seg = blk & 3;
    const float4* __restrict__ p =
        reinterpret_cast<const float4*>(x + (size_t)row * SPATIAL) + seg * SEG4;

    float ax = 0.f, ay = 0.f, az = 0.f, aw = 0.f;
    // 6912 / 256 = 27 iterations
#pragma unroll 9
    for (int i = threadIdx.x; i < SEG4; i += 256) {
        float4 v = p[i];
        ax += v.x; ay += v.y; az += v.z; aw += v.w;
    }
    float acc = (ax + ay) + (az + aw);

    for (int off = 16; off > 0; off >>= 1)
        acc += __shfl_down_sync(0xFFFFFFFFu, acc, off);

    __shared__ float warp_sums[8];
    const int lane = threadIdx.x & 31;
    const int wid  = threadIdx.x >> 5;
    if (lane == 0) warp_sums[wid] = acc;
    __syncthreads();

    if (threadIdx.x == 0) {
        float s = warp_sums[0] + warp_sums[1] + warp_sums[2] + warp_sums[3]
                + warp_sums[4] + warp_sums[5] + warp_sums[6] + warp_sums[7];
        partials[blk] = s;
        cudaTriggerProgrammaticLaunchCompletion();
    }
}

// ---------------------------------------------------------------------------
// Kernel 2 (PDL secondary): stages weights in smem BEFORE the grid-dependency
// sync, then (after partials are visible) runs the tiny MLP, a rank-based
// top-k pick, and copies the selected channel. grid = (6, 64), 512 threads.
// Every block runs the identical FP sequence => deterministic.
// ---------------------------------------------------------------------------
__global__ __launch_bounds__(GT) void gather_mlp_kernel(
    const float* __restrict__ x,
    const float* __restrict__ w1, const float* __restrict__ b1,
    const float* __restrict__ w2, const float* __restrict__ b2,
    const float* __restrict__ partials,
    float* __restrict__ out) {

    __shared__ float sw1[C * C];     // 16 KB
    __shared__ float sw2[C * C];     // 16 KB
    __shared__ float sb1[C], sb2[C];
    __shared__ float mb[C];
    __shared__ float y1s[C];
    __shared__ float zs[C];
    __shared__ int   ch_s;

    const int row = blockIdx.y;      // 0..63 : b*R + r
    const int b   = row >> 3;
    const int r   = row & 7;
    const int t   = threadIdx.x;
    const int lane = t & 31;
    const int wrp  = t >> 5;         // 0..15

    // ---- Pre-sync: stage weights/biases (overlaps kernel-1 tail) ---------
#pragma unroll
    for (int k = 0; k < 8; k++) {
        sw1[t + k * GT] = w1[t + k * GT];
        sw2[t + k * GT] = w2[t + k * GT];
    }
    if (t < C) { sb1[t] = b1[t]; sb2[t] = b2[t]; }

    // ---- Wait for kernel 1's partials -------------------------------------
    cudaGridDependencySynchronize();

    if (t < C) {
        float4 ps = reinterpret_cast<const float4*>(partials)[b * C + t];
        mb[t] = ((ps.x + ps.y) + (ps.z + ps.w)) * (1.0f / (float)SPATIAL);
    }
    __syncthreads();

    // layer 1: warp w -> channels 4w..4w+3 (smem weights, conflict-free)
    {
        const float m0 = mb[lane];
        const float m1 = mb[lane + 32];
#pragma unroll
        for (int c = 0; c < 4; c++) {
            const int i = 4 * wrp + c;
            float a = m0 * sw1[i * C + lane] + m1 * sw1[i * C + 32 + lane];
#pragma unroll
            for (int off = 16; off > 0; off >>= 1)
                a += __shfl_down_sync(0xFFFFFFFFu, a, off);
            if (lane == 0) {
                a += sb1[i];
                y1s[i] = (a > 0.0f) ? a : NEG_SLOPE * a;
            }
        }
    }
    __syncthreads();

    // layer 2: same with w2, sigmoid
    {
        const float h0 = y1s[lane];
        const float h1 = y1s[lane + 32];
#pragma unroll
        for (int c = 0; c < 4; c++) {
            const int i = 4 * wrp + c;
            float a = h0 * sw2[i * C + lane] + h1 * sw2[i * C + 32 + lane];
#pragma unroll
            for (int off = 16; off > 0; off >>= 1)
                a += __shfl_down_sync(0xFFFFFFFFu, a, off);
            if (lane == 0) {
                a += sb2[i];
                zs[i] = 1.0f / (1.0f + expf(-a));
            }
        }
    }
    __syncthreads();

    // Rank-based selection (warp 0): rank(j) = #{j' beats j}, where j' beats
    // j iff z[j'] > z[j] or (z[j'] == z[j] and j' < j). The channel with
    // rank == r is exactly the r-th pick of repeated strict-argmax with
    // smaller-index tie-break (jax.lax.top_k order).
    if (t < 32) {
        const float z0 = zs[t];
        const float z1 = zs[t + 32];
        int r0 = 0, r1 = 0;
#pragma unroll
        for (int jj = 0; jj < C; jj++) {
            const float v = zs[jj];
            r0 += (v > z0) || (v == z0 && jj < t);
            r1 += (v > z1) || (v == z1 && jj < t + 32);
        }
        if (r0 == r) ch_s = t;
        if (r1 == r) ch_s = t + 32;
    }
    __syncthreads();

    // Copy the selected channel: 9 float4 per thread, coalesced, exact cover.
    const int ch = ch_s;
    const float4* __restrict__ src =
        reinterpret_cast<const float4*>(x + ((size_t)b * C + ch) * SPATIAL);
    float4* __restrict__ dst =
        reinterpret_cast<float4*>(out) + (size_t)row * SPATIAL4;

#pragma unroll
    for (int k = 0; k < GK; k++) {
        const int i = (blockIdx.x * GK + k) * GT + t;  // 0..27647
        dst[i] = src[i];
    }
}

// ---------------------------------------------------------------------------
extern "C" void kernel_launch(void* const* d_in, const int* in_sizes, int n_in,
                              void* d_out, int out_size) {
    const float* x  = (const float*)d_in[0];
    const float* w1 = (const float*)d_in[1];
    const float* b1 = (const float*)d_in[2];
    const float* w2 = (const float*)d_in[3];
    const float* b2 = (const float*)d_in[4];
    float* out = (float*)d_out;

    float* partials;
    cudaGetSymbolAddress((void**)&partials, g_partials);

    mean_partial_kernel<<<NBLK1, 256>>>(x, partials);

    // PDL launch of the gather: it may start (and stage weights) while
    // kernel 1 drains; cudaGridDependencySynchronize() gates the partials.
    cudaLaunchConfig_t cfg = {};
    cfg.gridDim  = dim3(GBX, B * R, 1);   // (6, 64)
    cfg.blockDim = dim3(GT, 1, 1);
    cudaLaunchAttribute attrs[1];
    attrs[0].id = cudaLaunchAttributeProgrammaticStreamSerialization;
    attrs[0].val.programmaticStreamSerializationAllowed = 1;
    cfg.attrs = attrs;
    cfg.numAttrs = 1;
    cudaLaunchKernelEx(&cfg, gather_mlp_kernel, x, w1, b1, w2, b2,
                       (const float*)partials, out);
}